// round 7
// baseline (speedup 1.0000x reference)
#include <cuda_runtime.h>
#include <cuda_bf16.h>
#include <cstdint>

// ============================================================================
// DivFreeNetwork via mma.sync (bf16 HMMA, split-precision hi/lo, fp32 accum).
// R7: 32-row tiles (8 samples), 256 threads / 8 warps, 3 CTAs per SM.
// Warp w: all 32 rows, cols w*32.  Double-buffered 16-k weight chunks.
// ============================================================================

#define THREADS 256

// smem byte offsets
#define SM_A_HI 0
#define SM_A_LO 16896              // 32 * 528
#define SM_W0   33792
#define SM_W1   50688              // SM_W0 + 16896
#define SMEM_TOTAL 67584
#define ASTRIDE 528                // bytes per A row (264 bf16: 256 + 8 pad)
#define WSTRIDE 528
#define CHUNK_BYTES 16896          // 2 splits * 16 k * 528
#define LO_OFF 8448                // 16 * 528
#define CSTRIDE_F 264              // floats per C row

// Pre-baked weights: [chunk(64)][split(2)][16][264] bf16  (~1.03 MB)
__device__ __align__(16) __nv_bfloat16 g_w[64 * 2 * 16 * 264];

// ---------------------------------------------------------------------------
__device__ __forceinline__ uint32_t smem_u32(const void* p) {
    uint32_t a;
    asm("{ .reg .u64 t; cvta.to.shared.u64 t, %1; cvt.u32.u64 %0, t; }"
        : "=r"(a) : "l"(p));
    return a;
}
__device__ __forceinline__ void cp_async16(uint32_t saddr, const void* g) {
    asm volatile("cp.async.cg.shared.global [%0], [%1], 16;"
                 :: "r"(saddr), "l"(g) : "memory");
}
__device__ __forceinline__ void cp_commit() {
    asm volatile("cp.async.commit_group;" ::: "memory");
}
__device__ __forceinline__ void cp_wait_all() {
    asm volatile("cp.async.wait_group 0;" ::: "memory");
}

__device__ __forceinline__ void ldsm_x4(uint32_t* r, uint32_t addr) {
    asm volatile("ldmatrix.sync.aligned.m8n8.x4.shared.b16 {%0,%1,%2,%3}, [%4];"
                 : "=r"(r[0]), "=r"(r[1]), "=r"(r[2]), "=r"(r[3]) : "r"(addr));
}
__device__ __forceinline__ void ldsm_x4t(uint32_t* r, uint32_t addr) {
    asm volatile("ldmatrix.sync.aligned.m8n8.x4.trans.shared.b16 {%0,%1,%2,%3}, [%4];"
                 : "=r"(r[0]), "=r"(r[1]), "=r"(r[2]), "=r"(r[3]) : "r"(addr));
}
__device__ __forceinline__ void mma_bf16(float* d, const uint32_t* a, const uint32_t* b) {
    asm volatile(
        "mma.sync.aligned.m16n8k16.row.col.f32.bf16.bf16.f32 "
        "{%0,%1,%2,%3}, {%4,%5,%6,%7}, {%8,%9}, {%0,%1,%2,%3};"
        : "+f"(d[0]), "+f"(d[1]), "+f"(d[2]), "+f"(d[3])
        : "r"(a[0]), "r"(a[1]), "r"(a[2]), "r"(a[3]), "r"(b[0]), "r"(b[1]));
}

// hi/lo split of two fp32 into packed bf16x2 (low 16 bits = first element)
__device__ __forceinline__ void split2(float a0, float a1, uint32_t& hi, uint32_t& lo) {
    __nv_bfloat16 h0 = __float2bfloat16(a0);
    __nv_bfloat16 h1 = __float2bfloat16(a1);
    __nv_bfloat16 l0 = __float2bfloat16(a0 - __bfloat162float(h0));
    __nv_bfloat16 l1 = __float2bfloat16(a1 - __bfloat162float(h1));
    hi = ((uint32_t)__bfloat16_as_ushort(h1) << 16) | (uint32_t)__bfloat16_as_ushort(h0);
    lo = ((uint32_t)__bfloat16_as_ushort(l1) << 16) | (uint32_t)__bfloat16_as_ushort(l0);
}

// ---------------------------------------------------------------------------
// Prep: split weights into hi/lo bf16, transpose to [k][n] padded images.
// ---------------------------------------------------------------------------
__global__ void prep_kernel(const float* __restrict__ w_hid,
                            const float* __restrict__ w_out) {
    int e = blockIdx.x * blockDim.x + threadIdx.x;     // 0 .. 262143
    int l = e >> 16;
    int k = (e >> 8) & 255;
    int n = e & 255;
    const float* W = (l < 3) ? (w_hid + l * 65536) : w_out;
    float v = W[k * 256 + n];
    __nv_bfloat16 hi = __float2bfloat16(v);
    __nv_bfloat16 lo = __float2bfloat16(v - __bfloat162float(hi));
    int chunk = l * 16 + (k >> 4), kl = k & 15;
    size_t b0 = (((size_t)chunk * 2 + 0) * 16 + kl) * 264 + n;
    size_t b1 = (((size_t)chunk * 2 + 1) * 16 + kl) * 264 + n;
    g_w[b0] = hi;
    g_w[b1] = lo;
}

// ---------------------------------------------------------------------------
__global__ __launch_bounds__(THREADS, 3)
void divfree_main(const float* __restrict__ x,
                  const float* __restrict__ w_in,
                  const float* __restrict__ b_in,
                  const float* __restrict__ b_hid,
                  const float* __restrict__ b_out,
                  float* __restrict__ out)
{
    extern __shared__ char smem[];
    const uint32_t sb = smem_u32(smem);
    const int tid  = threadIdx.x;
    const int wid  = tid >> 5;
    const int lane = tid & 31;

    // ---- prefetch weight chunk 0 into buffer 0 ----
    {
        const char* src = (const char*)g_w;
        for (int i = tid; i < CHUNK_BYTES / 16; i += THREADS)
            cp_async16(sb + SM_W0 + (uint32_t)i * 16, src + (size_t)i * 16);
        cp_commit();
    }

    // ---- layer 0: z(3) -> 256, identity tangent seeds, silu ----
    for (int idx = tid; idx < 32 * 128; idx += THREADS) {
        int row = idx >> 7;
        int cp  = idx & 127;
        int c0  = cp * 2;
        int rt  = row & 3;
        int samp = blockIdx.x * 8 + (row >> 2);
        float z0 = __ldg(x + samp * 3 + 0);
        float z1 = __ldg(x + samp * 3 + 1);
        float z2 = __ldg(x + samp * 3 + 2);
        float a[2];
#pragma unroll
        for (int q = 0; q < 2; q++) {
            int c = c0 + q;
            float w0 = __ldg(w_in + c);
            float w1 = __ldg(w_in + 256 + c);
            float w2 = __ldg(w_in + 512 + c);
            float pre = __ldg(b_in + c) + z0 * w0 + z1 * w1 + z2 * w2;
            float sig = 1.f / (1.f + __expf(-pre));
            if (rt == 0) a[q] = pre * sig;
            else {
                float ds = sig * (1.f + pre * (1.f - sig));
                a[q] = ds * (rt == 1 ? w0 : (rt == 2 ? w1 : w2));
            }
        }
        uint32_t hi, lo;
        split2(a[0], a[1], hi, lo);
        *(uint32_t*)(smem + SM_A_HI + row * ASTRIDE + c0 * 2) = hi;
        *(uint32_t*)(smem + SM_A_LO + row * ASTRIDE + c0 * 2) = lo;
    }

    // ldmatrix base addresses (A: all 32 rows -> 2 m16 tiles, shared by warps)
    uint32_t aHiBase[2], aLoBase[2];
#pragma unroll
    for (int mt = 0; mt < 2; mt++) {
        int row = mt * 16 + (lane & 15);
        uint32_t off = (uint32_t)row * ASTRIDE + 16u * (lane >> 4);
        aHiBase[mt] = sb + SM_A_HI + off;
        aLoBase[mt] = sb + SM_A_LO + off;
    }
    // B: warp w owns cols w*32 .. w*32+31; x4t at +nt*32 bytes (16 cols each)
    const uint32_t bOff = (uint32_t)(lane & 15) * WSTRIDE
                          + ((uint32_t)wid * 32 + 8u * (lane >> 4)) * 2;

    const uint32_t vsrc  = (lane & 0x10) | (lane & 3);   // value-row lane in quad
    const bool     isval = (lane & 0xC) == 0;

    int c = 0;
    for (int L = 0; L < 4; L++) {
        float acc[2][4][4];
#pragma unroll
        for (int mt = 0; mt < 2; mt++)
#pragma unroll
            for (int nt = 0; nt < 4; nt++)
#pragma unroll
                for (int j = 0; j < 4; j++) acc[mt][nt][j] = 0.f;

        for (int kc = 0; kc < 16; kc++, c++) {
            cp_wait_all();
            __syncthreads();                  // chunk c ready; prior reads done
            const uint32_t wbuf = (c & 1) ? SM_W1 : SM_W0;

            if (c + 1 < 64) {                 // prefetch next chunk
                const char* src = (const char*)g_w + (size_t)(c + 1) * CHUNK_BYTES;
                const uint32_t dst = sb + ((c & 1) ? SM_W0 : SM_W1);
                for (int i = tid; i < CHUNK_BYTES / 16; i += THREADS)
                    cp_async16(dst + (uint32_t)i * 16, src + (size_t)i * 16);
                cp_commit();
            }

            const uint32_t k0b = (uint32_t)kc * 32;      // k offset in A (bytes)
            uint32_t ahi[2][4], alo[2][4];
            ldsm_x4(ahi[0], aHiBase[0] + k0b);
            ldsm_x4(ahi[1], aHiBase[1] + k0b);
            ldsm_x4(alo[0], aLoBase[0] + k0b);
            ldsm_x4(alo[1], aLoBase[1] + k0b);

            uint32_t bhi[2][4], blo[2][4];
            const uint32_t bk = sb + wbuf + bOff;
            ldsm_x4t(bhi[0], bk);
            ldsm_x4t(blo[0], bk + LO_OFF);
#pragma unroll
            for (int nt = 0; nt < 2; nt++) {
                int cur = nt & 1, nxt = cur ^ 1;
                if (nt < 1) {                 // prefetch next B fragments
                    uint32_t ba = bk + 32;
                    ldsm_x4t(bhi[nxt], ba);
                    ldsm_x4t(blo[nxt], ba + LO_OFF);
                }
#pragma unroll
                for (int mt = 0; mt < 2; mt++) {
                    mma_bf16(acc[mt][nt * 2],     ahi[mt], bhi[cur]);
                    mma_bf16(acc[mt][nt * 2 + 1], ahi[mt], bhi[cur] + 2);
                }
#pragma unroll
                for (int mt = 0; mt < 2; mt++) {
                    mma_bf16(acc[mt][nt * 2],     ahi[mt], blo[cur]);
                    mma_bf16(acc[mt][nt * 2 + 1], ahi[mt], blo[cur] + 2);
                }
#pragma unroll
                for (int mt = 0; mt < 2; mt++) {
                    mma_bf16(acc[mt][nt * 2],     alo[mt], bhi[cur]);
                    mma_bf16(acc[mt][nt * 2 + 1], alo[mt], bhi[cur] + 2);
                }
            }
        }
        __syncthreads();   // all A reads for this layer complete

        if (L < 3) {
            // ---- mid-layer epilogue: silu + tangent scaling -> A hi/lo ----
            const float* bias = b_hid + L * 256;
#pragma unroll
            for (int mt = 0; mt < 2; mt++) {
                int rlo = mt * 16 + (lane >> 2);
#pragma unroll
                for (int nt8 = 0; nt8 < 4; nt8++) {
                    int cc = wid * 32 + nt8 * 8 + (lane & 3) * 2;
                    float bv0 = __ldg(bias + cc);
                    float bv1 = __ldg(bias + cc + 1);
                    float* a4 = acc[mt][nt8];
                    float s0 = __shfl_sync(0xffffffffu, a4[0], vsrc);
                    float s1 = __shfl_sync(0xffffffffu, a4[1], vsrc);
                    float s2 = __shfl_sync(0xffffffffu, a4[2], vsrc);
                    float s3 = __shfl_sync(0xffffffffu, a4[3], vsrc);
                    float o[4];
                    const float bb[4] = {bv0, bv1, bv0, bv1};
                    const float ss[4] = {s0, s1, s2, s3};
#pragma unroll
                    for (int j = 0; j < 4; j++) {
                        float pre = ss[j] + bb[j];
                        float sig = 1.f / (1.f + __expf(-pre));
                        if (isval) o[j] = pre * sig;
                        else {
                            float ds = sig * (1.f + pre * (1.f - sig));
                            o[j] = ds * a4[j];
                        }
                    }
                    uint32_t hi, lo;
                    split2(o[0], o[1], hi, lo);
                    *(uint32_t*)(smem + SM_A_HI + rlo * ASTRIDE + cc * 2) = hi;
                    *(uint32_t*)(smem + SM_A_LO + rlo * ASTRIDE + cc * 2) = lo;
                    split2(o[2], o[3], hi, lo);
                    *(uint32_t*)(smem + SM_A_HI + (rlo + 8) * ASTRIDE + cc * 2) = hi;
                    *(uint32_t*)(smem + SM_A_LO + (rlo + 8) * ASTRIDE + cc * 2) = lo;
                }
            }
            __syncthreads();
        } else {
            // ---- final layer: dump fp32 C to smem (aliases A region) ----
            float* C = (float*)smem;
#pragma unroll
            for (int mt = 0; mt < 2; mt++) {
                int rlo = mt * 16 + (lane >> 2);
#pragma unroll
                for (int nt8 = 0; nt8 < 4; nt8++) {
                    int cc = wid * 32 + nt8 * 8 + (lane & 3) * 2;
                    float* a4 = acc[mt][nt8];
                    *(float2*)(C + rlo * CSTRIDE_F + cc)       = make_float2(a4[0], a4[1]);
                    *(float2*)(C + (rlo + 8) * CSTRIDE_F + cc) = make_float2(a4[2], a4[3]);
                }
            }
            __syncthreads();
        }
    }

    // ---- final epilogue: softmax mixture + JVP combine (warp 0) ----
    if (wid == 0) {
        const float* C = (const float*)smem;
        const int row  = lane;
        const int rt   = lane & 3;
        const int base = lane & ~3;
        const float* Crow = C + row * CSTRIDE_F;

        float E = 0.f, P0 = 0.f, P1 = 0.f, P2 = 0.f;
        float Q = 0.f, R0 = 0.f, R1 = 0.f, R2 = 0.f;
        float Mx = -1e30f;
        for (int cb = 0; cb < 8; cb++) {
            float4 q4[8];
#pragma unroll
            for (int m = 0; m < 8; m++)
                q4[m] = *(const float4*)(Crow + cb * 32 + m * 4);
            float lg[8];
            float cmax = -1e30f;
#pragma unroll
            for (int m = 0; m < 8; m++) {
                lg[m] = __shfl_sync(0xffffffffu, q4[m].x, base)
                        + __ldg(b_out + cb * 32 + m * 4);
                cmax = fmaxf(cmax, lg[m]);
            }
            float nM = fmaxf(Mx, cmax);
            float sc = __expf(Mx - nM);
            E *= sc; P0 *= sc; P1 *= sc; P2 *= sc;
            Q *= sc; R0 *= sc; R1 *= sc; R2 *= sc;
            Mx = nM;
#pragma unroll
            for (int m = 0; m < 8; m++) {
                float e = __expf(lg[m] - Mx);
                int c0 = cb * 32 + m * 4;
                float v0 = __shfl_sync(0xffffffffu, q4[m].y, base) + __ldg(b_out + c0 + 1);
                float v1 = __shfl_sync(0xffffffffu, q4[m].z, base) + __ldg(b_out + c0 + 2);
                float v2 = __shfl_sync(0xffffffffu, q4[m].w, base) + __ldg(b_out + c0 + 3);
                if (rt == 0) {
                    E += e; P0 += e * v0; P1 += e * v1; P2 += e * v2;
                } else {
                    float gl = q4[m].x;
                    Q  += e * gl;
                    R0 += e * (gl * v0 + q4[m].y);
                    R1 += e * (gl * v1 + q4[m].z);
                    R2 += e * (gl * v2 + q4[m].w);
                }
            }
        }
        float Ev = __shfl_sync(0xffffffffu, E, base);
        float p0 = __shfl_sync(0xffffffffu, P0, base);
        float p1 = __shfl_sync(0xffffffffu, P1, base);
        float p2 = __shfl_sync(0xffffffffu, P2, base);
        float inv = 1.f / Ev;
        float t0 = p0 * inv, t1 = p1 * inv, t2 = p2 * inv;
        float S  = Q * inv;
        float dt0 = R0 * inv - S * t0;
        float dt1 = R1 * inv - S * t1;
        float dt2 = R2 * inv - S * t2;
        // dtri[t][k] lives on lane base+1+k as dt{t}
        float d01 = __shfl_sync(0xffffffffu, dt0, base + 2);
        float d12 = __shfl_sync(0xffffffffu, dt1, base + 3);
        float d00 = __shfl_sync(0xffffffffu, dt0, base + 1);
        float d22 = __shfl_sync(0xffffffffu, dt2, base + 3);
        float d10 = __shfl_sync(0xffffffffu, dt1, base + 1);
        float d21 = __shfl_sync(0xffffffffu, dt2, base + 2);
        if (rt == 0) {
            int samp = blockIdx.x * 8 + (row >> 2);
            out[samp * 3 + 0] =  d01 + d12;
            out[samp * 3 + 1] = -d00 + d22;
            out[samp * 3 + 2] = -d10 - d21;
        }
    }
}

// ---------------------------------------------------------------------------
extern "C" void kernel_launch(void* const* d_in, const int* in_sizes, int n_in,
                              void* d_out, int out_size)
{
    const float* x     = (const float*)d_in[0];
    const float* w_in  = (const float*)d_in[1];
    const float* b_in  = (const float*)d_in[2];
    const float* w_hid = (const float*)d_in[3];
    const float* b_hid = (const float*)d_in[4];
    const float* w_out = (const float*)d_in[5];
    const float* b_out = (const float*)d_in[6];
    float*       out   = (float*)d_out;

    const int N = in_sizes[0] / 3;   // 65536 samples

    prep_kernel<<<1024, 256>>>(w_hid, w_out);

    cudaFuncSetAttribute(divfree_main,
                         cudaFuncAttributeMaxDynamicSharedMemorySize, SMEM_TOTAL);
    divfree_main<<<N / 8, THREADS, SMEM_TOTAL>>>(x, w_in, b_in, b_hid, b_out, out);
    (void)n_in; (void)out_size;
}

// round 9
// speedup vs baseline: 1.1359x; 1.1359x over previous
#include <cuda_runtime.h>
#include <cuda_bf16.h>
#include <cstdint>

// ============================================================================
// DivFreeNetwork via mma.sync (bf16 HMMA, split-precision hi/lo, fp32 accum).
// R8: R6 config (64-row tiles, 8 warps, 2 CTAs/SM) but warp-pair-decoupled:
// each pair (2w,2w+1) stages its private 64-col B slab per 16-k chunk and
// syncs with a 64-thread named barrier; CTA-wide sync only at layer bounds.
// ============================================================================

#define THREADS 256

// smem byte offsets
#define SM_A_HI 0
#define SM_A_LO 33792              // 64 * 528
#define SM_WP   67584              // 4 pairs * 2 bufs * 4608 = 36864
#define SMEM_TOTAL 104448
#define ASTRIDE 528                // bytes per A row (264 bf16: 256 + 8 pad)
#define PSTRIDE 144                // bytes per slab k-row (72 bf16: 64 + 8 pad)
#define SLAB_BYTES 4608            // 2 splits * 16 k * 144
#define SLAB_LO 2304               // 16 * 144
#define CSTRIDE_F 264              // floats per C row

// Pre-baked weights: [chunk(64)][pair(4)][split(2)][16][72] bf16  (~1.18 MB)
__device__ __align__(16) __nv_bfloat16 g_wp[64 * 4 * 2 * 16 * 72];

// ---------------------------------------------------------------------------
__device__ __forceinline__ uint32_t smem_u32(const void* p) {
    uint32_t a;
    asm("{ .reg .u64 t; cvta.to.shared.u64 t, %1; cvt.u32.u64 %0, t; }"
        : "=r"(a) : "l"(p));
    return a;
}
__device__ __forceinline__ void cp_async16(uint32_t saddr, const void* g) {
    asm volatile("cp.async.cg.shared.global [%0], [%1], 16;"
                 :: "r"(saddr), "l"(g) : "memory");
}
__device__ __forceinline__ void cp_commit() {
    asm volatile("cp.async.commit_group;" ::: "memory");
}
__device__ __forceinline__ void cp_wait_all() {
    asm volatile("cp.async.wait_group 0;" ::: "memory");
}
__device__ __forceinline__ void bar_pair(int id) {
    asm volatile("bar.sync %0, 64;" :: "r"(id) : "memory");
}

__device__ __forceinline__ void ldsm_x4(uint32_t* r, uint32_t addr) {
    asm volatile("ldmatrix.sync.aligned.m8n8.x4.shared.b16 {%0,%1,%2,%3}, [%4];"
                 : "=r"(r[0]), "=r"(r[1]), "=r"(r[2]), "=r"(r[3]) : "r"(addr));
}
__device__ __forceinline__ void ldsm_x4t(uint32_t* r, uint32_t addr) {
    asm volatile("ldmatrix.sync.aligned.m8n8.x4.trans.shared.b16 {%0,%1,%2,%3}, [%4];"
                 : "=r"(r[0]), "=r"(r[1]), "=r"(r[2]), "=r"(r[3]) : "r"(addr));
}
__device__ __forceinline__ void mma_bf16(float* d, const uint32_t* a, const uint32_t* b) {
    asm volatile(
        "mma.sync.aligned.m16n8k16.row.col.f32.bf16.bf16.f32 "
        "{%0,%1,%2,%3}, {%4,%5,%6,%7}, {%8,%9}, {%0,%1,%2,%3};"
        : "+f"(d[0]), "+f"(d[1]), "+f"(d[2]), "+f"(d[3])
        : "r"(a[0]), "r"(a[1]), "r"(a[2]), "r"(a[3]), "r"(b[0]), "r"(b[1]));
}

// hi/lo split of two fp32 into packed bf16x2 (low 16 bits = first element)
__device__ __forceinline__ void split2(float a0, float a1, uint32_t& hi, uint32_t& lo) {
    __nv_bfloat16 h0 = __float2bfloat16(a0);
    __nv_bfloat16 h1 = __float2bfloat16(a1);
    __nv_bfloat16 l0 = __float2bfloat16(a0 - __bfloat162float(h0));
    __nv_bfloat16 l1 = __float2bfloat16(a1 - __bfloat162float(h1));
    hi = ((uint32_t)__bfloat16_as_ushort(h1) << 16) | (uint32_t)__bfloat16_as_ushort(h0);
    lo = ((uint32_t)__bfloat16_as_ushort(l1) << 16) | (uint32_t)__bfloat16_as_ushort(l0);
}

// ---------------------------------------------------------------------------
// Prep: split weights into hi/lo bf16, transpose to per-pair [k][n] slabs.
// ---------------------------------------------------------------------------
__global__ void prep_kernel(const float* __restrict__ w_hid,
                            const float* __restrict__ w_out) {
    int e = blockIdx.x * blockDim.x + threadIdx.x;     // 0 .. 262143
    int l = e >> 16;
    int k = (e >> 8) & 255;
    int n = e & 255;
    const float* W = (l < 3) ? (w_hid + l * 65536) : w_out;
    float v = W[k * 256 + n];
    __nv_bfloat16 hi = __float2bfloat16(v);
    __nv_bfloat16 lo = __float2bfloat16(v - __bfloat162float(hi));
    int chunk = l * 16 + (k >> 4), kl = k & 15;
    int pair = n >> 6, nl = n & 63;
    size_t base = ((size_t)chunk * 4 + pair) * 2;
    g_wp[((base + 0) * 16 + kl) * 72 + nl] = hi;
    g_wp[((base + 1) * 16 + kl) * 72 + nl] = lo;
}

// ---------------------------------------------------------------------------
__global__ __launch_bounds__(THREADS, 2)
void divfree_main(const float* __restrict__ x,
                  const float* __restrict__ w_in,
                  const float* __restrict__ b_in,
                  const float* __restrict__ b_hid,
                  const float* __restrict__ b_out,
                  float* __restrict__ out)
{
    extern __shared__ char smem[];
    const uint32_t sb = smem_u32(smem);
    const int tid  = threadIdx.x;
    const int wid  = tid >> 5;
    const int lane = tid & 31;
    const int wm   = wid & 1;     // row group (32 rows of 64)
    const int pair = wid >> 1;    // col quarter (64 cols of 256)
    const int wp_tid = tid & 63;  // thread id within pair

    // ---- prefetch this pair's slab of chunk 0 into buffer 0 ----
    {
        const char* src = (const char*)g_wp + (size_t)pair * SLAB_BYTES;
        const uint32_t dst = sb + SM_WP + (uint32_t)(pair * 2) * SLAB_BYTES;
        for (int i = wp_tid; i < SLAB_BYTES / 16; i += 64)
            cp_async16(dst + (uint32_t)i * 16, src + (size_t)i * 16);
        cp_commit();
    }

    // ---- layer 0: z(3) -> 256, identity tangent seeds, silu ----
    for (int idx = tid; idx < 64 * 128; idx += THREADS) {
        int row = idx >> 7;
        int cp  = idx & 127;
        int c0  = cp * 2;
        int rt  = row & 3;
        int samp = blockIdx.x * 16 + (row >> 2);
        float z0 = __ldg(x + samp * 3 + 0);
        float z1 = __ldg(x + samp * 3 + 1);
        float z2 = __ldg(x + samp * 3 + 2);
        float a[2];
#pragma unroll
        for (int q = 0; q < 2; q++) {
            int c = c0 + q;
            float w0 = __ldg(w_in + c);
            float w1 = __ldg(w_in + 256 + c);
            float w2 = __ldg(w_in + 512 + c);
            float pre = __ldg(b_in + c) + z0 * w0 + z1 * w1 + z2 * w2;
            float sig = 1.f / (1.f + __expf(-pre));
            if (rt == 0) a[q] = pre * sig;
            else {
                float ds = sig * (1.f + pre * (1.f - sig));
                a[q] = ds * (rt == 1 ? w0 : (rt == 2 ? w1 : w2));
            }
        }
        uint32_t hi, lo;
        split2(a[0], a[1], hi, lo);
        *(uint32_t*)(smem + SM_A_HI + row * ASTRIDE + c0 * 2) = hi;
        *(uint32_t*)(smem + SM_A_LO + row * ASTRIDE + c0 * 2) = lo;
    }
    __syncthreads();                   // layer-0 A visible to all pairs

    // ldmatrix base addresses (A: 32 rows per warp -> 2 m16 tiles)
    uint32_t aHiBase[2], aLoBase[2];
#pragma unroll
    for (int mt = 0; mt < 2; mt++) {
        int row = wm * 32 + mt * 16 + (lane & 15);
        uint32_t off = (uint32_t)row * ASTRIDE + 16u * (lane >> 4);
        aHiBase[mt] = sb + SM_A_HI + off;
        aLoBase[mt] = sb + SM_A_LO + off;
    }
    // B (per-pair slab): addr = slab + (lane&15)*PSTRIDE + 16*(lane>>4) + nt*32
    const uint32_t bOff = (uint32_t)(lane & 15) * PSTRIDE + 16u * (lane >> 4);

    const uint32_t vsrc  = (lane & 0x10) | (lane & 3);   // value-row lane in quad
    const bool     isval = (lane & 0xC) == 0;

    int c = 0;
    for (int L = 0; L < 4; L++) {
        float acc[2][8][4];
#pragma unroll
        for (int mt = 0; mt < 2; mt++)
#pragma unroll
            for (int nt = 0; nt < 8; nt++)
#pragma unroll
                for (int j = 0; j < 4; j++) acc[mt][nt][j] = 0.f;

        for (int kc = 0; kc < 16; kc++, c++) {
            cp_wait_all();
            bar_pair(pair + 1);           // pair's slab ready, prior reads done

            if (c + 1 < 64) {             // prefetch this pair's next slab
                const char* src = (const char*)g_wp
                    + ((size_t)(c + 1) * 4 + pair) * SLAB_BYTES;
                const uint32_t dst = sb + SM_WP
                    + (uint32_t)(pair * 2 + ((c + 1) & 1)) * SLAB_BYTES;
                for (int i = wp_tid; i < SLAB_BYTES / 16; i += 64)
                    cp_async16(dst + (uint32_t)i * 16, src + (size_t)i * 16);
                cp_commit();
            }

            const uint32_t slab = sb + SM_WP
                + (uint32_t)(pair * 2 + (c & 1)) * SLAB_BYTES;
            const uint32_t bk  = slab + bOff;
            const uint32_t k0b = (uint32_t)kc * 32;      // k offset in A (bytes)

            uint32_t ahi[2][4], alo[2][4];
            ldsm_x4(ahi[0], aHiBase[0] + k0b);
            ldsm_x4(ahi[1], aHiBase[1] + k0b);
            ldsm_x4(alo[0], aLoBase[0] + k0b);
            ldsm_x4(alo[1], aLoBase[1] + k0b);

            uint32_t bhi[2][4], blo[2][4];
            ldsm_x4t(bhi[0], bk);
            ldsm_x4t(blo[0], bk + SLAB_LO);
#pragma unroll
            for (int nt = 0; nt < 4; nt++) {
                int cur = nt & 1, nxt = cur ^ 1;
                if (nt < 3) {                 // prefetch next B fragments
                    uint32_t ba = bk + (uint32_t)(nt + 1) * 32;
                    ldsm_x4t(bhi[nxt], ba);
                    ldsm_x4t(blo[nxt], ba + SLAB_LO);
                }
#pragma unroll
                for (int mt = 0; mt < 2; mt++) {
                    mma_bf16(acc[mt][nt * 2],     ahi[mt], bhi[cur]);
                    mma_bf16(acc[mt][nt * 2 + 1], ahi[mt], bhi[cur] + 2);
                }
#pragma unroll
                for (int mt = 0; mt < 2; mt++) {
                    mma_bf16(acc[mt][nt * 2],     ahi[mt], blo[cur]);
                    mma_bf16(acc[mt][nt * 2 + 1], ahi[mt], blo[cur] + 2);
                }
#pragma unroll
                for (int mt = 0; mt < 2; mt++) {
                    mma_bf16(acc[mt][nt * 2],     alo[mt], bhi[cur]);
                    mma_bf16(acc[mt][nt * 2 + 1], alo[mt], bhi[cur] + 2);
                }
            }
        }
        __syncthreads();   // all pairs done reading this layer's A

        if (L < 3) {
            // ---- mid-layer epilogue: silu + tangent scaling -> A hi/lo ----
            const float* bias = b_hid + L * 256;
#pragma unroll
            for (int mt = 0; mt < 2; mt++) {
                int rlo = wm * 32 + mt * 16 + (lane >> 2);
#pragma unroll
                for (int nt8 = 0; nt8 < 8; nt8++) {
                    int cc = pair * 64 + nt8 * 8 + (lane & 3) * 2;
                    float bv0 = __ldg(bias + cc);
                    float bv1 = __ldg(bias + cc + 1);
                    float* a4 = acc[mt][nt8];
                    float s0 = __shfl_sync(0xffffffffu, a4[0], vsrc);
                    float s1 = __shfl_sync(0xffffffffu, a4[1], vsrc);
                    float s2 = __shfl_sync(0xffffffffu, a4[2], vsrc);
                    float s3 = __shfl_sync(0xffffffffu, a4[3], vsrc);
                    float o[4];
                    const float bb[4] = {bv0, bv1, bv0, bv1};
                    const float ss[4] = {s0, s1, s2, s3};
#pragma unroll
                    for (int j = 0; j < 4; j++) {
                        float pre = ss[j] + bb[j];
                        float sig = 1.f / (1.f + __expf(-pre));
                        if (isval) o[j] = pre * sig;
                        else {
                            float ds = sig * (1.f + pre * (1.f - sig));
                            o[j] = ds * a4[j];
                        }
                    }
                    uint32_t hi, lo;
                    split2(o[0], o[1], hi, lo);
                    *(uint32_t*)(smem + SM_A_HI + rlo * ASTRIDE + cc * 2) = hi;
                    *(uint32_t*)(smem + SM_A_LO + rlo * ASTRIDE + cc * 2) = lo;
                    split2(o[2], o[3], hi, lo);
                    *(uint32_t*)(smem + SM_A_HI + (rlo + 8) * ASTRIDE + cc * 2) = hi;
                    *(uint32_t*)(smem + SM_A_LO + (rlo + 8) * ASTRIDE + cc * 2) = lo;
                }
            }
            __syncthreads();
        } else {
            // ---- final layer: dump fp32 C to smem (aliases A region) ----
            float* C = (float*)smem;
#pragma unroll
            for (int mt = 0; mt < 2; mt++) {
                int rlo = wm * 32 + mt * 16 + (lane >> 2);
#pragma unroll
                for (int nt8 = 0; nt8 < 8; nt8++) {
                    int cc = pair * 64 + nt8 * 8 + (lane & 3) * 2;
                    float* a4 = acc[mt][nt8];
                    *(float2*)(C + rlo * CSTRIDE_F + cc)       = make_float2(a4[0], a4[1]);
                    *(float2*)(C + (rlo + 8) * CSTRIDE_F + cc) = make_float2(a4[2], a4[3]);
                }
            }
            __syncthreads();
        }
    }

    // ---- final epilogue: softmax mixture + JVP combine (warps 0-1) ----
    if (wid < 2) {
        const float* C = (const float*)smem;
        const int row  = wid * 32 + lane;
        const int rt   = lane & 3;
        const int base = lane & ~3;
        const float* Crow = C + row * CSTRIDE_F;

        float E = 0.f, P0 = 0.f, P1 = 0.f, P2 = 0.f;
        float Q = 0.f, R0 = 0.f, R1 = 0.f, R2 = 0.f;
        float Mx = -1e30f;
        for (int cb = 0; cb < 8; cb++) {
            float4 q4[8];
#pragma unroll
            for (int m = 0; m < 8; m++)
                q4[m] = *(const float4*)(Crow + cb * 32 + m * 4);
            float lg[8];
            float cmax = -1e30f;
#pragma unroll
            for (int m = 0; m < 8; m++) {
                lg[m] = __shfl_sync(0xffffffffu, q4[m].x, base)
                        + __ldg(b_out + cb * 32 + m * 4);
                cmax = fmaxf(cmax, lg[m]);
            }
            float nM = fmaxf(Mx, cmax);
            float sc = __expf(Mx - nM);
            E *= sc; P0 *= sc; P1 *= sc; P2 *= sc;
            Q *= sc; R0 *= sc; R1 *= sc; R2 *= sc;
            Mx = nM;
#pragma unroll
            for (int m = 0; m < 8; m++) {
                float e = __expf(lg[m] - Mx);
                int c0 = cb * 32 + m * 4;
                float v0 = __shfl_sync(0xffffffffu, q4[m].y, base) + __ldg(b_out + c0 + 1);
                float v1 = __shfl_sync(0xffffffffu, q4[m].z, base) + __ldg(b_out + c0 + 2);
                float v2 = __shfl_sync(0xffffffffu, q4[m].w, base) + __ldg(b_out + c0 + 3);
                if (rt == 0) {
                    E += e; P0 += e * v0; P1 += e * v1; P2 += e * v2;
                } else {
                    float gl = q4[m].x;
                    Q  += e * gl;
                    R0 += e * (gl * v0 + q4[m].y);
                    R1 += e * (gl * v1 + q4[m].z);
                    R2 += e * (gl * v2 + q4[m].w);
                }
            }
        }
        float Ev = __shfl_sync(0xffffffffu, E, base);
        float p0 = __shfl_sync(0xffffffffu, P0, base);
        float p1 = __shfl_sync(0xffffffffu, P1, base);
        float p2 = __shfl_sync(0xffffffffu, P2, base);
        float inv = 1.f / Ev;
        float t0 = p0 * inv, t1 = p1 * inv, t2 = p2 * inv;
        float S  = Q * inv;
        float dt0 = R0 * inv - S * t0;
        float dt1 = R1 * inv - S * t1;
        float dt2 = R2 * inv - S * t2;
        // dtri[t][k] lives on lane base+1+k as dt{t}
        float d01 = __shfl_sync(0xffffffffu, dt0, base + 2);
        float d12 = __shfl_sync(0xffffffffu, dt1, base + 3);
        float d00 = __shfl_sync(0xffffffffu, dt0, base + 1);
        float d22 = __shfl_sync(0xffffffffu, dt2, base + 3);
        float d10 = __shfl_sync(0xffffffffu, dt1, base + 1);
        float d21 = __shfl_sync(0xffffffffu, dt2, base + 2);
        if (rt == 0) {
            int samp = blockIdx.x * 16 + (row >> 2);
            out[samp * 3 + 0] =  d01 + d12;
            out[samp * 3 + 1] = -d00 + d22;
            out[samp * 3 + 2] = -d10 - d21;
        }
    }
}

// ---------------------------------------------------------------------------
extern "C" void kernel_launch(void* const* d_in, const int* in_sizes, int n_in,
                              void* d_out, int out_size)
{
    const float* x     = (const float*)d_in[0];
    const float* w_in  = (const float*)d_in[1];
    const float* b_in  = (const float*)d_in[2];
    const float* w_hid = (const float*)d_in[3];
    const float* b_hid = (const float*)d_in[4];
    const float* w_out = (const float*)d_in[5];
    const float* b_out = (const float*)d_in[6];
    float*       out   = (float*)d_out;

    const int N = in_sizes[0] / 3;   // 65536 samples

    prep_kernel<<<1024, 256>>>(w_hid, w_out);

    cudaFuncSetAttribute(divfree_main,
                         cudaFuncAttributeMaxDynamicSharedMemorySize, SMEM_TOTAL);
    divfree_main<<<N / 16, THREADS, SMEM_TOTAL>>>(x, w_in, b_in, b_hid, b_out, out);
    (void)n_in; (void)out_size;
}

// round 11
// speedup vs baseline: 1.1562x; 1.0179x over previous
#include <cuda_runtime.h>
#include <cuda_bf16.h>
#include <cstdint>

// ============================================================================
// DivFreeNetwork via mma.sync (bf16 HMMA, split-precision hi/lo, fp32 accum).
// R10: R8 base (64-row tiles, 8 warps, 2 CTAs/SM, pair-decoupled B slabs)
// + A-ldsm hoisted above the chunk wait, bf16x2 packing cvt, vector bias loads.
// ============================================================================

#define THREADS 256

// smem byte offsets
#define SM_A_HI 0
#define SM_A_LO 33792              // 64 * 528
#define SM_WP   67584              // 4 pairs * 2 bufs * 4608 = 36864
#define SMEM_TOTAL 104448
#define ASTRIDE 528                // bytes per A row (264 bf16: 256 + 8 pad)
#define PSTRIDE 144                // bytes per slab k-row (72 bf16: 64 + 8 pad)
#define SLAB_BYTES 4608            // 2 splits * 16 k * 144
#define SLAB_LO 2304               // 16 * 144
#define CSTRIDE_F 264              // floats per C row

// Pre-baked weights: [chunk(64)][pair(4)][split(2)][16][72] bf16  (~1.18 MB)
__device__ __align__(16) __nv_bfloat16 g_wp[64 * 4 * 2 * 16 * 72];

// ---------------------------------------------------------------------------
__device__ __forceinline__ uint32_t smem_u32(const void* p) {
    uint32_t a;
    asm("{ .reg .u64 t; cvta.to.shared.u64 t, %1; cvt.u32.u64 %0, t; }"
        : "=r"(a) : "l"(p));
    return a;
}
__device__ __forceinline__ void cp_async16(uint32_t saddr, const void* g) {
    asm volatile("cp.async.cg.shared.global [%0], [%1], 16;"
                 :: "r"(saddr), "l"(g) : "memory");
}
__device__ __forceinline__ void cp_commit() {
    asm volatile("cp.async.commit_group;" ::: "memory");
}
__device__ __forceinline__ void cp_wait_all() {
    asm volatile("cp.async.wait_group 0;" ::: "memory");
}
__device__ __forceinline__ void bar_pair(int id) {
    asm volatile("bar.sync %0, 64;" :: "r"(id) : "memory");
}

__device__ __forceinline__ void ldsm_x4(uint32_t* r, uint32_t addr) {
    asm volatile("ldmatrix.sync.aligned.m8n8.x4.shared.b16 {%0,%1,%2,%3}, [%4];"
                 : "=r"(r[0]), "=r"(r[1]), "=r"(r[2]), "=r"(r[3]) : "r"(addr));
}
__device__ __forceinline__ void ldsm_x4t(uint32_t* r, uint32_t addr) {
    asm volatile("ldmatrix.sync.aligned.m8n8.x4.trans.shared.b16 {%0,%1,%2,%3}, [%4];"
                 : "=r"(r[0]), "=r"(r[1]), "=r"(r[2]), "=r"(r[3]) : "r"(addr));
}
__device__ __forceinline__ void mma_bf16(float* d, const uint32_t* a, const uint32_t* b) {
    asm volatile(
        "mma.sync.aligned.m16n8k16.row.col.f32.bf16.bf16.f32 "
        "{%0,%1,%2,%3}, {%4,%5,%6,%7}, {%8,%9}, {%0,%1,%2,%3};"
        : "+f"(d[0]), "+f"(d[1]), "+f"(d[2]), "+f"(d[3])
        : "r"(a[0]), "r"(a[1]), "r"(a[2]), "r"(a[3]), "r"(b[0]), "r"(b[1]));
}

// hi/lo split of two fp32 into packed bf16x2 (low 16 bits = first element)
__device__ __forceinline__ void split2(float a0, float a1, uint32_t& hi, uint32_t& lo) {
    asm("cvt.rn.bf16x2.f32 %0, %1, %2;" : "=r"(hi) : "f"(a1), "f"(a0));
    float h0 = __uint_as_float(hi << 16);
    float h1 = __uint_as_float(hi & 0xffff0000u);
    float r0 = a0 - h0;
    float r1 = a1 - h1;
    asm("cvt.rn.bf16x2.f32 %0, %1, %2;" : "=r"(lo) : "f"(r1), "f"(r0));
}

// ---------------------------------------------------------------------------
// Prep: split weights into hi/lo bf16, transpose to per-pair [k][n] slabs.
// ---------------------------------------------------------------------------
__global__ void prep_kernel(const float* __restrict__ w_hid,
                            const float* __restrict__ w_out) {
    int e = blockIdx.x * blockDim.x + threadIdx.x;     // 0 .. 262143
    int l = e >> 16;
    int k = (e >> 8) & 255;
    int n = e & 255;
    const float* W = (l < 3) ? (w_hid + l * 65536) : w_out;
    float v = W[k * 256 + n];
    __nv_bfloat16 hi = __float2bfloat16(v);
    __nv_bfloat16 lo = __float2bfloat16(v - __bfloat162float(hi));
    int chunk = l * 16 + (k >> 4), kl = k & 15;
    int pair = n >> 6, nl = n & 63;
    size_t base = ((size_t)chunk * 4 + pair) * 2;
    g_wp[((base + 0) * 16 + kl) * 72 + nl] = hi;
    g_wp[((base + 1) * 16 + kl) * 72 + nl] = lo;
}

// ---------------------------------------------------------------------------
__global__ __launch_bounds__(THREADS, 2)
void divfree_main(const float* __restrict__ x,
                  const float* __restrict__ w_in,
                  const float* __restrict__ b_in,
                  const float* __restrict__ b_hid,
                  const float* __restrict__ b_out,
                  float* __restrict__ out)
{
    extern __shared__ char smem[];
    const uint32_t sb = smem_u32(smem);
    const int tid  = threadIdx.x;
    const int wid  = tid >> 5;
    const int lane = tid & 31;
    const int wm   = wid & 1;     // row group (32 rows of 64)
    const int pair = wid >> 1;    // col quarter (64 cols of 256)
    const int wp_tid = tid & 63;  // thread id within pair

    // ---- prefetch this pair's slab of chunk 0 into buffer 0 ----
    {
        const char* src = (const char*)g_wp + (size_t)pair * SLAB_BYTES;
        const uint32_t dst = sb + SM_WP + (uint32_t)(pair * 2) * SLAB_BYTES;
        for (int i = wp_tid; i < SLAB_BYTES / 16; i += 64)
            cp_async16(dst + (uint32_t)i * 16, src + (size_t)i * 16);
        cp_commit();
    }

    // ---- layer 0: z(3) -> 256, identity tangent seeds, silu ----
    for (int idx = tid; idx < 64 * 128; idx += THREADS) {
        int row = idx >> 7;
        int cp  = idx & 127;
        int c0  = cp * 2;
        int rt  = row & 3;
        int samp = blockIdx.x * 16 + (row >> 2);
        float z0 = __ldg(x + samp * 3 + 0);
        float z1 = __ldg(x + samp * 3 + 1);
        float z2 = __ldg(x + samp * 3 + 2);
        float a[2];
#pragma unroll
        for (int q = 0; q < 2; q++) {
            int c = c0 + q;
            float w0 = __ldg(w_in + c);
            float w1 = __ldg(w_in + 256 + c);
            float w2 = __ldg(w_in + 512 + c);
            float pre = __ldg(b_in + c) + z0 * w0 + z1 * w1 + z2 * w2;
            float sig = 1.f / (1.f + __expf(-pre));
            if (rt == 0) a[q] = pre * sig;
            else {
                float ds = sig * (1.f + pre * (1.f - sig));
                a[q] = ds * (rt == 1 ? w0 : (rt == 2 ? w1 : w2));
            }
        }
        uint32_t hi, lo;
        split2(a[0], a[1], hi, lo);
        *(uint32_t*)(smem + SM_A_HI + row * ASTRIDE + c0 * 2) = hi;
        *(uint32_t*)(smem + SM_A_LO + row * ASTRIDE + c0 * 2) = lo;
    }
    __syncthreads();                   // layer-0 A visible to all pairs

    // ldmatrix base addresses (A: 32 rows per warp -> 2 m16 tiles)
    uint32_t aHiBase[2], aLoBase[2];
#pragma unroll
    for (int mt = 0; mt < 2; mt++) {
        int row = wm * 32 + mt * 16 + (lane & 15);
        uint32_t off = (uint32_t)row * ASTRIDE + 16u * (lane >> 4);
        aHiBase[mt] = sb + SM_A_HI + off;
        aLoBase[mt] = sb + SM_A_LO + off;
    }
    // B (per-pair slab): addr = slab + (lane&15)*PSTRIDE + 16*(lane>>4) + nt*32
    const uint32_t bOff = (uint32_t)(lane & 15) * PSTRIDE + 16u * (lane >> 4);

    const uint32_t vsrc  = (lane & 0x10) | (lane & 3);   // value-row lane in quad
    const bool     isval = (lane & 0xC) == 0;

    int c = 0;
    for (int L = 0; L < 4; L++) {
        float acc[2][8][4];
#pragma unroll
        for (int mt = 0; mt < 2; mt++)
#pragma unroll
            for (int nt = 0; nt < 8; nt++)
#pragma unroll
                for (int j = 0; j < 4; j++) acc[mt][nt][j] = 0.f;

        for (int kc = 0; kc < 16; kc++, c++) {
            // A fragments are layer-stable: issue their loads BEFORE the wait
            // so LDS latency overlaps the B-slab arrival + barrier.
            const uint32_t k0b = (uint32_t)kc * 32;      // k offset in A (bytes)
            uint32_t ahi[2][4], alo[2][4];
            ldsm_x4(ahi[0], aHiBase[0] + k0b);
            ldsm_x4(ahi[1], aHiBase[1] + k0b);
            ldsm_x4(alo[0], aLoBase[0] + k0b);
            ldsm_x4(alo[1], aLoBase[1] + k0b);

            cp_wait_all();
            bar_pair(pair + 1);           // pair's slab ready, prior reads done

            if (c + 1 < 64) {             // prefetch this pair's next slab
                const char* src = (const char*)g_wp
                    + ((size_t)(c + 1) * 4 + pair) * SLAB_BYTES;
                const uint32_t dst = sb + SM_WP
                    + (uint32_t)(pair * 2 + ((c + 1) & 1)) * SLAB_BYTES;
                for (int i = wp_tid; i < SLAB_BYTES / 16; i += 64)
                    cp_async16(dst + (uint32_t)i * 16, src + (size_t)i * 16);
                cp_commit();
            }

            const uint32_t slab = sb + SM_WP
                + (uint32_t)(pair * 2 + (c & 1)) * SLAB_BYTES;
            const uint32_t bk  = slab + bOff;

            uint32_t bhi[2][4], blo[2][4];
            ldsm_x4t(bhi[0], bk);
            ldsm_x4t(blo[0], bk + SLAB_LO);
#pragma unroll
            for (int nt = 0; nt < 4; nt++) {
                int cur = nt & 1, nxt = cur ^ 1;
                if (nt < 3) {                 // prefetch next B fragments
                    uint32_t ba = bk + (uint32_t)(nt + 1) * 32;
                    ldsm_x4t(bhi[nxt], ba);
                    ldsm_x4t(blo[nxt], ba + SLAB_LO);
                }
#pragma unroll
                for (int mt = 0; mt < 2; mt++) {
                    mma_bf16(acc[mt][nt * 2],     ahi[mt], bhi[cur]);
                    mma_bf16(acc[mt][nt * 2 + 1], ahi[mt], bhi[cur] + 2);
                }
#pragma unroll
                for (int mt = 0; mt < 2; mt++) {
                    mma_bf16(acc[mt][nt * 2],     ahi[mt], blo[cur]);
                    mma_bf16(acc[mt][nt * 2 + 1], ahi[mt], blo[cur] + 2);
                }
#pragma unroll
                for (int mt = 0; mt < 2; mt++) {
                    mma_bf16(acc[mt][nt * 2],     alo[mt], bhi[cur]);
                    mma_bf16(acc[mt][nt * 2 + 1], alo[mt], bhi[cur] + 2);
                }
            }
        }
        __syncthreads();   // all pairs done reading this layer's A

        if (L < 3) {
            // ---- mid-layer epilogue: silu + tangent scaling -> A hi/lo ----
            const float* bias = b_hid + L * 256;
#pragma unroll
            for (int mt = 0; mt < 2; mt++) {
                int rlo = wm * 32 + mt * 16 + (lane >> 2);
#pragma unroll
                for (int nt8 = 0; nt8 < 8; nt8++) {
                    int cc = pair * 64 + nt8 * 8 + (lane & 3) * 2;
                    float2 bv = *(const float2*)(bias + cc);
                    float* a4 = acc[mt][nt8];
                    float s0 = __shfl_sync(0xffffffffu, a4[0], vsrc);
                    float s1 = __shfl_sync(0xffffffffu, a4[1], vsrc);
                    float s2 = __shfl_sync(0xffffffffu, a4[2], vsrc);
                    float s3 = __shfl_sync(0xffffffffu, a4[3], vsrc);
                    float o[4];
                    const float bb[4] = {bv.x, bv.y, bv.x, bv.y};
                    const float ss[4] = {s0, s1, s2, s3};
#pragma unroll
                    for (int j = 0; j < 4; j++) {
                        float pre = ss[j] + bb[j];
                        float sig = 1.f / (1.f + __expf(-pre));
                        if (isval) o[j] = pre * sig;
                        else {
                            float ds = sig * (1.f + pre * (1.f - sig));
                            o[j] = ds * a4[j];
                        }
                    }
                    uint32_t hi, lo;
                    split2(o[0], o[1], hi, lo);
                    *(uint32_t*)(smem + SM_A_HI + rlo * ASTRIDE + cc * 2) = hi;
                    *(uint32_t*)(smem + SM_A_LO + rlo * ASTRIDE + cc * 2) = lo;
                    split2(o[2], o[3], hi, lo);
                    *(uint32_t*)(smem + SM_A_HI + (rlo + 8) * ASTRIDE + cc * 2) = hi;
                    *(uint32_t*)(smem + SM_A_LO + (rlo + 8) * ASTRIDE + cc * 2) = lo;
                }
            }
            __syncthreads();
        } else {
            // ---- final layer: dump fp32 C to smem (aliases A region) ----
            float* C = (float*)smem;
#pragma unroll
            for (int mt = 0; mt < 2; mt++) {
                int rlo = wm * 32 + mt * 16 + (lane >> 2);
#pragma unroll
                for (int nt8 = 0; nt8 < 8; nt8++) {
                    int cc = pair * 64 + nt8 * 8 + (lane & 3) * 2;
                    float* a4 = acc[mt][nt8];
                    *(float2*)(C + rlo * CSTRIDE_F + cc)       = make_float2(a4[0], a4[1]);
                    *(float2*)(C + (rlo + 8) * CSTRIDE_F + cc) = make_float2(a4[2], a4[3]);
                }
            }
            __syncthreads();
        }
    }

    // ---- final epilogue: softmax mixture + JVP combine (warps 0-1) ----
    if (wid < 2) {
        const float* C = (const float*)smem;
        const int row  = wid * 32 + lane;
        const int rt   = lane & 3;
        const int base = lane & ~3;
        const float* Crow = C + row * CSTRIDE_F;

        float E = 0.f, P0 = 0.f, P1 = 0.f, P2 = 0.f;
        float Q = 0.f, R0 = 0.f, R1 = 0.f, R2 = 0.f;
        float Mx = -1e30f;
        for (int cb = 0; cb < 8; cb++) {
            float4 q4[8];
#pragma unroll
            for (int m = 0; m < 8; m++)
                q4[m] = *(const float4*)(Crow + cb * 32 + m * 4);
            float lg[8];
            float cmax = -1e30f;
#pragma unroll
            for (int m = 0; m < 8; m++) {
                lg[m] = __shfl_sync(0xffffffffu, q4[m].x, base)
                        + __ldg(b_out + cb * 32 + m * 4);
                cmax = fmaxf(cmax, lg[m]);
            }
            float nM = fmaxf(Mx, cmax);
            float sc = __expf(Mx - nM);
            E *= sc; P0 *= sc; P1 *= sc; P2 *= sc;
            Q *= sc; R0 *= sc; R1 *= sc; R2 *= sc;
            Mx = nM;
#pragma unroll
            for (int m = 0; m < 8; m++) {
                float e = __expf(lg[m] - Mx);
                int c0 = cb * 32 + m * 4;
                float4 bo = *(const float4*)(b_out + c0);
                float v0 = __shfl_sync(0xffffffffu, q4[m].y, base) + bo.y;
                float v1 = __shfl_sync(0xffffffffu, q4[m].z, base) + bo.z;
                float v2 = __shfl_sync(0xffffffffu, q4[m].w, base) + bo.w;
                if (rt == 0) {
                    E += e; P0 += e * v0; P1 += e * v1; P2 += e * v2;
                } else {
                    float gl = q4[m].x;
                    Q  += e * gl;
                    R0 += e * (gl * v0 + q4[m].y);
                    R1 += e * (gl * v1 + q4[m].z);
                    R2 += e * (gl * v2 + q4[m].w);
                }
            }
        }
        float Ev = __shfl_sync(0xffffffffu, E, base);
        float p0 = __shfl_sync(0xffffffffu, P0, base);
        float p1 = __shfl_sync(0xffffffffu, P1, base);
        float p2 = __shfl_sync(0xffffffffu, P2, base);
        float inv = 1.f / Ev;
        float t0 = p0 * inv, t1 = p1 * inv, t2 = p2 * inv;
        float S  = Q * inv;
        float dt0 = R0 * inv - S * t0;
        float dt1 = R1 * inv - S * t1;
        float dt2 = R2 * inv - S * t2;
        // dtri[t][k] lives on lane base+1+k as dt{t}
        float d01 = __shfl_sync(0xffffffffu, dt0, base + 2);
        float d12 = __shfl_sync(0xffffffffu, dt1, base + 3);
        float d00 = __shfl_sync(0xffffffffu, dt0, base + 1);
        float d22 = __shfl_sync(0xffffffffu, dt2, base + 3);
        float d10 = __shfl_sync(0xffffffffu, dt1, base + 1);
        float d21 = __shfl_sync(0xffffffffu, dt2, base + 2);
        if (rt == 0) {
            int samp = blockIdx.x * 16 + (row >> 2);
            out[samp * 3 + 0] =  d01 + d12;
            out[samp * 3 + 1] = -d00 + d22;
            out[samp * 3 + 2] = -d10 - d21;
        }
    }
}

// ---------------------------------------------------------------------------
extern "C" void kernel_launch(void* const* d_in, const int* in_sizes, int n_in,
                              void* d_out, int out_size)
{
    const float* x     = (const float*)d_in[0];
    const float* w_in  = (const float*)d_in[1];
    const float* b_in  = (const float*)d_in[2];
    const float* w_hid = (const float*)d_in[3];
    const float* b_hid = (const float*)d_in[4];
    const float* w_out = (const float*)d_in[5];
    const float* b_out = (const float*)d_in[6];
    float*       out   = (float*)d_out;

    const int N = in_sizes[0] / 3;   // 65536 samples

    prep_kernel<<<1024, 256>>>(w_hid, w_out);

    cudaFuncSetAttribute(divfree_main,
                         cudaFuncAttributeMaxDynamicSharedMemorySize, SMEM_TOTAL);
    divfree_main<<<N / 16, THREADS, SMEM_TOTAL>>>(x, w_in, b_in, b_hid, b_out, out);
    (void)n_in; (void)out_size;
}

// round 12
// speedup vs baseline: 1.9274x; 1.6670x over previous
#include <cuda_runtime.h>
#include <cuda_fp16.h>
#include <cstdint>

// ============================================================================
// DivFreeNetwork via mma.sync m16n8k16 fp16 (single-pass, fp32 accum).
// R12: R10 skeleton (64-row tiles, 8 warps, 2 CTAs/SM, pair-decoupled slabs)
// with single-precision-pass fp16 operands: 1/3 the MMAs of the split scheme.
// 32-k chunks (32 total), slab 4.6KB/pair/chunk, named-barrier pair sync.
// ============================================================================

#define THREADS 256

// smem byte offsets
#define SM_A    0                  // fp16 A image, 64 * 528
#define SM_WP   33792              // 4 pairs * 2 bufs * 4608 = 36864
#define SMEM_TOTAL 70656
#define ASTRIDE 528                // bytes per A row (264 fp16: 256 + 8 pad)
#define PSTRIDE 144                // bytes per slab k-row (72 fp16: 64 + 8 pad)
#define SLAB_BYTES 4608            // 32 k * 144
#define CSTRIDE_F 264              // floats per C row

// Pre-baked weights: [chunk(32)][pair(4)][32k][72] fp16  (~0.59 MB)
__device__ __align__(16) __half g_wp[32 * 4 * 32 * 72];

// ---------------------------------------------------------------------------
__device__ __forceinline__ uint32_t smem_u32(const void* p) {
    uint32_t a;
    asm("{ .reg .u64 t; cvta.to.shared.u64 t, %1; cvt.u32.u64 %0, t; }"
        : "=r"(a) : "l"(p));
    return a;
}
__device__ __forceinline__ void cp_async16(uint32_t saddr, const void* g) {
    asm volatile("cp.async.cg.shared.global [%0], [%1], 16;"
                 :: "r"(saddr), "l"(g) : "memory");
}
__device__ __forceinline__ void cp_commit() {
    asm volatile("cp.async.commit_group;" ::: "memory");
}
__device__ __forceinline__ void cp_wait_all() {
    asm volatile("cp.async.wait_group 0;" ::: "memory");
}
__device__ __forceinline__ void bar_pair(int id) {
    asm volatile("bar.sync %0, 64;" :: "r"(id) : "memory");
}

__device__ __forceinline__ void ldsm_x4(uint32_t* r, uint32_t addr) {
    asm volatile("ldmatrix.sync.aligned.m8n8.x4.shared.b16 {%0,%1,%2,%3}, [%4];"
                 : "=r"(r[0]), "=r"(r[1]), "=r"(r[2]), "=r"(r[3]) : "r"(addr));
}
__device__ __forceinline__ void ldsm_x4t(uint32_t* r, uint32_t addr) {
    asm volatile("ldmatrix.sync.aligned.m8n8.x4.trans.shared.b16 {%0,%1,%2,%3}, [%4];"
                 : "=r"(r[0]), "=r"(r[1]), "=r"(r[2]), "=r"(r[3]) : "r"(addr));
}
__device__ __forceinline__ void mma_f16(float* d, const uint32_t* a, const uint32_t* b) {
    asm volatile(
        "mma.sync.aligned.m16n8k16.row.col.f32.f16.f16.f32 "
        "{%0,%1,%2,%3}, {%4,%5,%6,%7}, {%8,%9}, {%0,%1,%2,%3};"
        : "+f"(d[0]), "+f"(d[1]), "+f"(d[2]), "+f"(d[3])
        : "r"(a[0]), "r"(a[1]), "r"(a[2]), "r"(a[3]), "r"(b[0]), "r"(b[1]));
}

// pack two fp32 into fp16x2 (low 16 bits = first element)
__device__ __forceinline__ uint32_t packh2(float a0, float a1) {
    uint32_t r;
    asm("cvt.rn.f16x2.f32 %0, %1, %2;" : "=r"(r) : "f"(a1), "f"(a0));
    return r;
}

// ---------------------------------------------------------------------------
// Prep: convert weights to fp16, transpose to per-pair [k][n] slabs.
// ---------------------------------------------------------------------------
__global__ void prep_kernel(const float* __restrict__ w_hid,
                            const float* __restrict__ w_out) {
    int e = blockIdx.x * blockDim.x + threadIdx.x;     // 0 .. 262143
    int l = e >> 16;
    int k = (e >> 8) & 255;
    int n = e & 255;
    const float* W = (l < 3) ? (w_hid + l * 65536) : w_out;
    float v = W[k * 256 + n];
    int chunk = l * 8 + (k >> 5), kl = k & 31;
    int pair = n >> 6, nl = n & 63;
    g_wp[(((size_t)chunk * 4 + pair) * 32 + kl) * 72 + nl] = __float2half(v);
}

// ---------------------------------------------------------------------------
__global__ __launch_bounds__(THREADS, 2)
void divfree_main(const float* __restrict__ x,
                  const float* __restrict__ w_in,
                  const float* __restrict__ b_in,
                  const float* __restrict__ b_hid,
                  const float* __restrict__ b_out,
                  float* __restrict__ out)
{
    extern __shared__ char smem[];
    const uint32_t sb = smem_u32(smem);
    const int tid  = threadIdx.x;
    const int wid  = tid >> 5;
    const int lane = tid & 31;
    const int wm   = wid & 1;     // row group (32 rows of 64)
    const int pair = wid >> 1;    // col quarter (64 cols of 256)
    const int wp_tid = tid & 63;  // thread id within pair

    // ---- prefetch this pair's slab of chunk 0 into buffer 0 ----
    {
        const char* src = (const char*)g_wp + (size_t)pair * SLAB_BYTES;
        const uint32_t dst = sb + SM_WP + (uint32_t)(pair * 2) * SLAB_BYTES;
        for (int i = wp_tid; i < SLAB_BYTES / 16; i += 64)
            cp_async16(dst + (uint32_t)i * 16, src + (size_t)i * 16);
        cp_commit();
    }

    // ---- layer 0: z(3) -> 256, identity tangent seeds, silu ----
    for (int idx = tid; idx < 64 * 128; idx += THREADS) {
        int row = idx >> 7;
        int cp  = idx & 127;
        int c0  = cp * 2;
        int rt  = row & 3;
        int samp = blockIdx.x * 16 + (row >> 2);
        float z0 = __ldg(x + samp * 3 + 0);
        float z1 = __ldg(x + samp * 3 + 1);
        float z2 = __ldg(x + samp * 3 + 2);
        float a[2];
#pragma unroll
        for (int q = 0; q < 2; q++) {
            int c = c0 + q;
            float w0 = __ldg(w_in + c);
            float w1 = __ldg(w_in + 256 + c);
            float w2 = __ldg(w_in + 512 + c);
            float pre = __ldg(b_in + c) + z0 * w0 + z1 * w1 + z2 * w2;
            float sig = 1.f / (1.f + __expf(-pre));
            if (rt == 0) a[q] = pre * sig;
            else {
                float ds = sig * (1.f + pre * (1.f - sig));
                a[q] = ds * (rt == 1 ? w0 : (rt == 2 ? w1 : w2));
            }
        }
        *(uint32_t*)(smem + SM_A + row * ASTRIDE + c0 * 2) = packh2(a[0], a[1]);
    }
    __syncthreads();                   // layer-0 A visible to all pairs

    // ldmatrix base addresses (A: 32 rows per warp -> 2 m16 tiles)
    uint32_t aBase[2];
#pragma unroll
    for (int mt = 0; mt < 2; mt++) {
        int row = wm * 32 + mt * 16 + (lane & 15);
        aBase[mt] = sb + SM_A + (uint32_t)row * ASTRIDE + 16u * (lane >> 4);
    }
    // B (per-pair slab): addr = slab + (lane&15)*PSTRIDE + 16*(lane>>4)
    //                         + k16*16*PSTRIDE + nt*32
    const uint32_t bOff = (uint32_t)(lane & 15) * PSTRIDE + 16u * (lane >> 4);

    const uint32_t vsrc  = (lane & 0x10) | (lane & 3);   // value-row lane in quad
    const bool     isval = (lane & 0xC) == 0;

    int c = 0;
    for (int L = 0; L < 4; L++) {
        float acc[2][8][4];
#pragma unroll
        for (int mt = 0; mt < 2; mt++)
#pragma unroll
            for (int nt = 0; nt < 8; nt++)
#pragma unroll
                for (int j = 0; j < 4; j++) acc[mt][nt][j] = 0.f;

        for (int kc = 0; kc < 8; kc++, c++) {
            // A fragments are layer-stable: load before the wait so LDS
            // latency overlaps the B-slab arrival + barrier.
            const uint32_t k0b = (uint32_t)kc * 64;      // 32 k = 64 bytes
            uint32_t a[2][2][4];                          // [k16][mt][4]
            ldsm_x4(a[0][0], aBase[0] + k0b);
            ldsm_x4(a[0][1], aBase[1] + k0b);
            ldsm_x4(a[1][0], aBase[0] + k0b + 32);
            ldsm_x4(a[1][1], aBase[1] + k0b + 32);

            cp_wait_all();
            bar_pair(pair + 1);           // pair's slab ready, prior reads done

            if (c + 1 < 32) {             // prefetch this pair's next slab
                const char* src = (const char*)g_wp
                    + ((size_t)(c + 1) * 4 + pair) * SLAB_BYTES;
                const uint32_t dst = sb + SM_WP
                    + (uint32_t)(pair * 2 + ((c + 1) & 1)) * SLAB_BYTES;
                for (int i = wp_tid; i < SLAB_BYTES / 16; i += 64)
                    cp_async16(dst + (uint32_t)i * 16, src + (size_t)i * 16);
                cp_commit();
            }

            const uint32_t bk = sb + SM_WP
                + (uint32_t)(pair * 2 + (c & 1)) * SLAB_BYTES + bOff;
#pragma unroll
            for (int k16 = 0; k16 < 2; k16++) {
                uint32_t b[4][4];
                const uint32_t bka = bk + (uint32_t)k16 * (16 * PSTRIDE);
                ldsm_x4t(b[0], bka);
                ldsm_x4t(b[1], bka + 32);
                ldsm_x4t(b[2], bka + 64);
                ldsm_x4t(b[3], bka + 96);
#pragma unroll
                for (int q = 0; q < 4; q++) {
#pragma unroll
                    for (int mt = 0; mt < 2; mt++) {
                        mma_f16(acc[mt][q * 2],     a[k16][mt], b[q]);
                        mma_f16(acc[mt][q * 2 + 1], a[k16][mt], b[q] + 2);
                    }
                }
            }
        }
        __syncthreads();   // all pairs done reading this layer's A

        if (L < 3) {
            // ---- mid-layer epilogue: silu + tangent scaling -> A fp16 ----
            const float* bias = b_hid + L * 256;
#pragma unroll
            for (int mt = 0; mt < 2; mt++) {
                int rlo = wm * 32 + mt * 16 + (lane >> 2);
#pragma unroll
                for (int nt8 = 0; nt8 < 8; nt8++) {
                    int cc = pair * 64 + nt8 * 8 + (lane & 3) * 2;
                    float2 bv = *(const float2*)(bias + cc);
                    float* a4 = acc[mt][nt8];
                    float s0 = __shfl_sync(0xffffffffu, a4[0], vsrc);
                    float s1 = __shfl_sync(0xffffffffu, a4[1], vsrc);
                    float s2 = __shfl_sync(0xffffffffu, a4[2], vsrc);
                    float s3 = __shfl_sync(0xffffffffu, a4[3], vsrc);
                    float o[4];
                    const float bb[4] = {bv.x, bv.y, bv.x, bv.y};
                    const float ss[4] = {s0, s1, s2, s3};
#pragma unroll
                    for (int j = 0; j < 4; j++) {
                        float pre = ss[j] + bb[j];
                        float sig = 1.f / (1.f + __expf(-pre));
                        if (isval) o[j] = pre * sig;
                        else {
                            float ds = sig * (1.f + pre * (1.f - sig));
                            o[j] = ds * a4[j];
                        }
                    }
                    *(uint32_t*)(smem + SM_A + rlo * ASTRIDE + cc * 2)
                        = packh2(o[0], o[1]);
                    *(uint32_t*)(smem + SM_A + (rlo + 8) * ASTRIDE + cc * 2)
                        = packh2(o[2], o[3]);
                }
            }
            __syncthreads();
        } else {
            // ---- final layer: dump fp32 C to smem (aliases A+slab region) ----
            float* C = (float*)smem;
#pragma unroll
            for (int mt = 0; mt < 2; mt++) {
                int rlo = wm * 32 + mt * 16 + (lane >> 2);
#pragma unroll
                for (int nt8 = 0; nt8 < 8; nt8++) {
                    int cc = pair * 64 + nt8 * 8 + (lane & 3) * 2;
                    float* a4 = acc[mt][nt8];
                    *(float2*)(C + rlo * CSTRIDE_F + cc)       = make_float2(a4[0], a4[1]);
                    *(float2*)(C + (rlo + 8) * CSTRIDE_F + cc) = make_float2(a4[2], a4[3]);
                }
            }
            __syncthreads();
        }
    }

    // ---- final epilogue: softmax mixture + JVP combine (warps 0-1) ----
    if (wid < 2) {
        const float* C = (const float*)smem;
        const int row  = wid * 32 + lane;
        const int rt   = lane & 3;
        const int base = lane & ~3;
        const float* Crow = C + row * CSTRIDE_F;

        float E = 0.f, P0 = 0.f, P1 = 0.f, P2 = 0.f;
        float Q = 0.f, R0 = 0.f, R1 = 0.f, R2 = 0.f;
        float Mx = -1e30f;
        for (int cb = 0; cb < 8; cb++) {
            float4 q4[8];
#pragma unroll
            for (int m = 0; m < 8; m++)
                q4[m] = *(const float4*)(Crow + cb * 32 + m * 4);
            float lg[8];
            float cmax = -1e30f;
#pragma unroll
            for (int m = 0; m < 8; m++) {
                lg[m] = __shfl_sync(0xffffffffu, q4[m].x, base)
                        + __ldg(b_out + cb * 32 + m * 4);
                cmax = fmaxf(cmax, lg[m]);
            }
            float nM = fmaxf(Mx, cmax);
            float sc = __expf(Mx - nM);
            E *= sc; P0 *= sc; P1 *= sc; P2 *= sc;
            Q *= sc; R0 *= sc; R1 *= sc; R2 *= sc;
            Mx = nM;
#pragma unroll
            for (int m = 0; m < 8; m++) {
                float e = __expf(lg[m] - Mx);
                int c0 = cb * 32 + m * 4;
                float4 bo = *(const float4*)(b_out + c0);
                float v0 = __shfl_sync(0xffffffffu, q4[m].y, base) + bo.y;
                float v1 = __shfl_sync(0xffffffffu, q4[m].z, base) + bo.z;
                float v2 = __shfl_sync(0xffffffffu, q4[m].w, base) + bo.w;
                if (rt == 0) {
                    E += e; P0 += e * v0; P1 += e * v1; P2 += e * v2;
                } else {
                    float gl = q4[m].x;
                    Q  += e * gl;
                    R0 += e * (gl * v0 + q4[m].y);
                    R1 += e * (gl * v1 + q4[m].z);
                    R2 += e * (gl * v2 + q4[m].w);
                }
            }
        }
        float Ev = __shfl_sync(0xffffffffu, E, base);
        float p0 = __shfl_sync(0xffffffffu, P0, base);
        float p1 = __shfl_sync(0xffffffffu, P1, base);
        float p2 = __shfl_sync(0xffffffffu, P2, base);
        float inv = 1.f / Ev;
        float t0 = p0 * inv, t1 = p1 * inv, t2 = p2 * inv;
        float S  = Q * inv;
        float dt0 = R0 * inv - S * t0;
        float dt1 = R1 * inv - S * t1;
        float dt2 = R2 * inv - S * t2;
        // dtri[t][k] lives on lane base+1+k as dt{t}
        float d01 = __shfl_sync(0xffffffffu, dt0, base + 2);
        float d12 = __shfl_sync(0xffffffffu, dt1, base + 3);
        float d00 = __shfl_sync(0xffffffffu, dt0, base + 1);
        float d22 = __shfl_sync(0xffffffffu, dt2, base + 3);
        float d10 = __shfl_sync(0xffffffffu, dt1, base + 1);
        float d21 = __shfl_sync(0xffffffffu, dt2, base + 2);
        if (rt == 0) {
            int samp = blockIdx.x * 16 + (row >> 2);
            out[samp * 3 + 0] =  d01 + d12;
            out[samp * 3 + 1] = -d00 + d22;
            out[samp * 3 + 2] = -d10 - d21;
        }
    }
}

// ---------------------------------------------------------------------------
extern "C" void kernel_launch(void* const* d_in, const int* in_sizes, int n_in,
                              void* d_out, int out_size)
{
    const float* x     = (const float*)d_in[0];
    const float* w_in  = (const float*)d_in[1];
    const float* b_in  = (const float*)d_in[2];
    const float* w_hid = (const float*)d_in[3];
    const float* b_hid = (const float*)d_in[4];
    const float* w_out = (const float*)d_in[5];
    const float* b_out = (const float*)d_in[6];
    float*       out   = (float*)d_out;

    const int N = in_sizes[0] / 3;   // 65536 samples

    prep_kernel<<<1024, 256>>>(w_hid, w_out);

    cudaFuncSetAttribute(divfree_main,
                         cudaFuncAttributeMaxDynamicSharedMemorySize, SMEM_TOTAL);
    divfree_main<<<N / 16, THREADS, SMEM_TOTAL>>>(x, w_in, b_in, b_hid, b_out, out);
    (void)n_in; (void)out_size;
}